// round 14
// baseline (speedup 1.0000x reference)
#include <cuda_runtime.h>
#include <cuda_fp8.h>
#include <cuda_fp16.h>
#include <cstdint>

#define NTOK 4096
#define HH   1024
#define VV   32000
#define VSP  125          // 125 * 256 = 32000 vocab splits
#define TTL  32           // 32 * 128 = 4096 token tiles
#define NKC  8            // 8 * 128 = 1024 k-chunks (fp8: 128 elems = 128B)
#define ROWB 128          // 128 fp8 per row, XOR-swizzled
#define ATILE (128*ROWB)  // 16384
#define BTILE (256*ROWB)  // 32768
#define STGB  (ATILE+BTILE) // 49152
#define DSMEM (2*STGB + 128)

// ---------------- device scratch (no allocations allowed) -------------------
__device__ __align__(256) unsigned char g_xb[(size_t)2*NTOK*HH];   // 8.4 MB
__device__ __align__(256) unsigned char g_wb[(size_t)2*VV*HH];     // 65.5 MB
__device__ float g_pm[(size_t)2*NTOK*VSP];
__device__ float g_ps[(size_t)2*NTOK*VSP];
__device__ float g_sel[2*NTOK];
__device__ float g_bsum[512];
__device__ float g_bmsk[512];

__device__ __forceinline__ uint32_t smem_u32(const void* p){
    uint32_t a;
    asm("{ .reg .u64 t; cvta.to.shared.u64 t, %1; cvt.u32.u64 %0, t; }" : "=r"(a) : "l"(p));
    return a;
}

// ================= fp32 -> e4m3 conversion (linear layout) ==================
__global__ void k_convert(const float* __restrict__ s0, const float* __restrict__ s1,
                          unsigned char* __restrict__ dst, size_t per_model_vec4){
    size_t g = (size_t)blockIdx.x*blockDim.x + threadIdx.x;
    if (g >= 2*per_model_vec4) return;
    int m = (int)(g / per_model_vec4);
    size_t i = g - (size_t)m*per_model_vec4;
    const float* src = m ? s1 : s0;
    float4 v = reinterpret_cast<const float4*>(src)[i];
    __nv_fp8x2_storage_t lo = __nv_cvt_float2_to_fp8x2(make_float2(v.x, v.y), __NV_SATFINITE, __NV_E4M3);
    __nv_fp8x2_storage_t hi = __nv_cvt_float2_to_fp8x2(make_float2(v.z, v.w), __NV_SATFINITE, __NV_E4M3);
    uint32_t o = (uint32_t)lo | ((uint32_t)hi << 16);
    reinterpret_cast<uint32_t*>(dst + (size_t)m*per_model_vec4*4)[i] = o;
}

// ================= main GEMM (mma e4m3 k32, f16 acc) + fused online-LSE =====
// grid (VSP=125, TTL=32, 2), block 256, CTA tile 128x256, warp tile 64x64.
// R12 pipeline + per-warp ks phase staggering to interleave LDSM/HMMA bursts.
__global__ void __launch_bounds__(256,2) k_gemm(){
    extern __shared__ __align__(16) unsigned char dsm[];
    const int tid = threadIdx.x, wid = tid>>5, lane = tid&31;
    const int vs = blockIdx.x, tt = blockIdx.y, model = blockIdx.z;
    const int wm = wid>>2, wn = wid&3;
    const int ks0 = wid & 3;   // per-warp ks phase offset
    const uint32_t s0 = (smem_u32(dsm) + 127) & ~127u;
    const unsigned char* asrc0 = g_xb + ((size_t)model*NTOK + (size_t)tt*128)*HH;
    const unsigned char* bsrc0 = g_wb + ((size_t)model*VV   + (size_t)vs*256)*HH;

    const int lq  = tid >> 3;
    const int lg  = tid & 7;
    const uint32_t dA = s0 + lq*ROWB + ((lg ^ (lq & 7)) << 4);
    const uint32_t dB = dA + ATILE;
    const unsigned char* srcA = asrc0 + (size_t)lq*HH + lg*16;
    const unsigned char* srcB = bsrc0 + (size_t)lq*HH + lg*16;

    #define LOADC(kc, so_) do{ \
        const size_t _ko = (size_t)(kc)*128; \
        _Pragma("unroll") \
        for (int it = 0; it < 4; it++) \
            asm volatile("cp.async.cg.shared.global [%0], [%1], 16;" \
                :: "r"(dA + (so_) + it*4096), "l"(srcA + _ko + (size_t)it*32768)); \
        _Pragma("unroll") \
        for (int it = 0; it < 8; it++) \
            asm volatile("cp.async.cg.shared.global [%0], [%1], 16;" \
                :: "r"(dB + (so_) + it*4096), "l"(srcB + _ko + (size_t)it*32768)); \
        asm volatile("cp.async.commit_group;"); \
    }while(0)

    uint32_t KA[4], KB[4];
    {
        const uint32_t half_a = (lane>>4) << 4;
        #pragma unroll
        for (int mt = 0; mt < 4; mt++){
            int row = wm*64 + mt*16 + (lane&15);
            KA[mt] = (s0 + row*ROWB + ((row&7)<<4)) ^ half_a;
        }
        const uint32_t half_b = ((lane>>3)&1) << 4;
        #pragma unroll
        for (int p = 0; p < 4; p++){
            int row = wn*64 + p*16 + (lane&7) + ((lane>>4)<<3);
            KB[p] = (s0 + ATILE + row*ROWB + ((row&7)<<4)) ^ half_b;
        }
    }

    uint32_t acc[4][8][2];
    #pragma unroll
    for (int a=0;a<4;a++)
        #pragma unroll
        for (int b=0;b<8;b++){ acc[a][b][0]=0u; acc[a][b][1]=0u; }

    LOADC(0, 0);
    LOADC(1, STGB);
    uint32_t rso = 0;
    #pragma unroll 1
    for (int kc = 0; kc < NKC; kc++){
        if (kc < NKC-1) asm volatile("cp.async.wait_group 1;");
        else            asm volatile("cp.async.wait_group 0;");
        __syncthreads();
        const uint32_t ar0 = KA[0]+rso, ar1 = KA[1]+rso, ar2 = KA[2]+rso, ar3 = KA[3]+rso;
        const uint32_t br0 = KB[0]+rso, br1 = KB[1]+rso, br2 = KB[2]+rso, br3 = KB[3]+rso;
        #pragma unroll
        for (int ksi = 0; ksi < 4; ksi++){
            const uint32_t xc = (uint32_t)(((ksi + ks0) & 3) << 5);  // staggered ks
            uint32_t af[4][4], bf[4][4];
            asm volatile("ldmatrix.sync.aligned.m8n8.x4.shared.b16 {%0,%1,%2,%3}, [%4];"
                : "=r"(af[0][0]),"=r"(af[0][1]),"=r"(af[0][2]),"=r"(af[0][3]) : "r"(ar0^xc));
            asm volatile("ldmatrix.sync.aligned.m8n8.x4.shared.b16 {%0,%1,%2,%3}, [%4];"
                : "=r"(af[1][0]),"=r"(af[1][1]),"=r"(af[1][2]),"=r"(af[1][3]) : "r"(ar1^xc));
            asm volatile("ldmatrix.sync.aligned.m8n8.x4.shared.b16 {%0,%1,%2,%3}, [%4];"
                : "=r"(af[2][0]),"=r"(af[2][1]),"=r"(af[2][2]),"=r"(af[2][3]) : "r"(ar2^xc));
            asm volatile("ldmatrix.sync.aligned.m8n8.x4.shared.b16 {%0,%1,%2,%3}, [%4];"
                : "=r"(af[3][0]),"=r"(af[3][1]),"=r"(af[3][2]),"=r"(af[3][3]) : "r"(ar3^xc));
            asm volatile("ldmatrix.sync.aligned.m8n8.x4.shared.b16 {%0,%1,%2,%3}, [%4];"
                : "=r"(bf[0][0]),"=r"(bf[0][1]),"=r"(bf[0][2]),"=r"(bf[0][3]) : "r"(br0^xc));
            asm volatile("ldmatrix.sync.aligned.m8n8.x4.shared.b16 {%0,%1,%2,%3}, [%4];"
                : "=r"(bf[1][0]),"=r"(bf[1][1]),"=r"(bf[1][2]),"=r"(bf[1][3]) : "r"(br1^xc));
            asm volatile("ldmatrix.sync.aligned.m8n8.x4.shared.b16 {%0,%1,%2,%3}, [%4];"
                : "=r"(bf[2][0]),"=r"(bf[2][1]),"=r"(bf[2][2]),"=r"(bf[2][3]) : "r"(br2^xc));
            asm volatile("ldmatrix.sync.aligned.m8n8.x4.shared.b16 {%0,%1,%2,%3}, [%4];"
                : "=r"(bf[3][0]),"=r"(bf[3][1]),"=r"(bf[3][2]),"=r"(bf[3][3]) : "r"(br3^xc));
            #pragma unroll
            for (int mt = 0; mt < 4; mt++)
                #pragma unroll
                for (int nt = 0; nt < 8; nt++){
                    uint32_t c0 = bf[nt>>1][(nt&1)*2], c1 = bf[nt>>1][(nt&1)*2+1];
                    asm volatile("mma.sync.aligned.m16n8k32.row.col.f16.e4m3.e4m3.f16 "
                        "{%0,%1}, {%2,%3,%4,%5}, {%6,%7}, {%0,%1};"
                        : "+r"(acc[mt][nt][0]),"+r"(acc[mt][nt][1])
                        : "r"(af[mt][0]),"r"(af[mt][1]),"r"(af[mt][2]),"r"(af[mt][3]),
                          "r"(c0),"r"(c1));
                }
        }
        __syncthreads();
        if (kc + 2 < NKC) LOADC(kc+2, rso);
        rso ^= STGB;
    }
    __syncthreads();

    // ---- fused epilogue: per-token-row (max, sumexp) over this 256-col slab -
    float* smM = (float*)dsm;
    float* smS = smM + 8*64;
    int q = lane>>2;
    #pragma unroll
    for (int mt = 0; mt < 4; mt++){
        float m0=-3e38f, m1=-3e38f;
        #pragma unroll
        for (int nt = 0; nt < 8; nt++){
            __half2 h0 = *reinterpret_cast<__half2*>(&acc[mt][nt][0]);
            __half2 h1 = *reinterpret_cast<__half2*>(&acc[mt][nt][1]);
            m0 = fmaxf(m0, fmaxf(__half2float(h0.x), __half2float(h0.y)));
            m1 = fmaxf(m1, fmaxf(__half2float(h1.x), __half2float(h1.y)));
        }
        #pragma unroll
        for (int o = 1; o <= 2; o <<= 1){
            m0 = fmaxf(m0, __shfl_xor_sync(0xFFFFFFFFu, m0, o));
            m1 = fmaxf(m1, __shfl_xor_sync(0xFFFFFFFFu, m1, o));
        }
        float sA = 0.f, sB = 0.f;
        #pragma unroll
        for (int nt = 0; nt < 8; nt++){
            __half2 h0 = *reinterpret_cast<__half2*>(&acc[mt][nt][0]);
            __half2 h1 = *reinterpret_cast<__half2*>(&acc[mt][nt][1]);
            sA += __expf(__half2float(h0.x)-m0) + __expf(__half2float(h0.y)-m0);
            sB += __expf(__half2float(h1.x)-m1) + __expf(__half2float(h1.y)-m1);
        }
        #pragma unroll
        for (int o = 1; o <= 2; o <<= 1){
            sA += __shfl_xor_sync(0xFFFFFFFFu, sA, o);
            sB += __shfl_xor_sync(0xFFFFFFFFu, sB, o);
        }
        if ((lane&3) == 0){
            int r = mt*16 + q;
            smM[wid*64 + r]     = m0;  smS[wid*64 + r]     = sA;
            smM[wid*64 + r + 8] = m1;  smS[wid*64 + r + 8] = sB;
        }
    }
    __syncthreads();
    if (tid < 128){
        int wm2 = tid>>6, r = tid&63;
        float M = -3e38f;
        #pragma unroll
        for (int w = 0; w < 4; w++) M = fmaxf(M, smM[(wm2*4+w)*64 + r]);
        float S = 0.f;
        #pragma unroll
        for (int w = 0; w < 4; w++) S += smS[(wm2*4+w)*64 + r] * __expf(smM[(wm2*4+w)*64 + r] - M);
        int tok = tt*128 + tid;
        size_t o = ((size_t)(model*NTOK + tok))*VSP + vs;
        g_pm[o] = M; g_ps[o] = S;
    }
}

// ================= exact fp32 selected logits ================================
__global__ void k_sel(const float* __restrict__ x, const float* __restrict__ w,
                      const float* __restrict__ rx, const float* __restrict__ rw,
                      const int* __restrict__ ids){
    int gw = (int)((blockIdx.x*blockDim.x + threadIdx.x) >> 5);
    int lane = threadIdx.x & 31;
    if (gw >= 2*NTOK) return;
    int m = gw >> 12, t = gw & (NTOK-1);
    const float* X = m ? rx : x;
    const float* W = m ? rw : w;
    int id = ids[t];
    const float4* xa = (const float4*)(X + (size_t)t*HH);
    const float4* wa = (const float4*)(W + (size_t)id*HH);
    float acc = 0.f;
    #pragma unroll 8
    for (int i = lane; i < 256; i += 32){
        float4 a = xa[i], b = wa[i];
        acc += a.x*b.x + a.y*b.y + a.z*b.z + a.w*b.w;
    }
    #pragma unroll
    for (int o = 16; o; o >>= 1) acc += __shfl_xor_sync(0xFFFFFFFFu, acc, o);
    if (!lane) g_sel[gw] = acc;
}

// ================= warp-per-token loss + deterministic block sums ===========
__global__ void k_reduce(const float* __restrict__ adv, const int* __restrict__ mask){
    const int lane = threadIdx.x & 31, wwid = threadIdx.x >> 5;
    const int t = blockIdx.x*8 + wwid;
    float lse[2];
    #pragma unroll
    for (int m = 0; m < 2; m++){
        const float* pm = g_pm + ((size_t)(m*NTOK + t))*VSP;
        const float* ps = g_ps + ((size_t)(m*NTOK + t))*VSP;
        float mx = -3e38f;
        #pragma unroll
        for (int v = lane; v < VSP; v += 32) mx = fmaxf(mx, pm[v]);
        #pragma unroll
        for (int o = 16; o; o >>= 1) mx = fmaxf(mx, __shfl_xor_sync(0xFFFFFFFFu, mx, o));
        float sv = 0.f;
        #pragma unroll
        for (int v = lane; v < VSP; v += 32) sv += ps[v] * __expf(pm[v] - mx);
        #pragma unroll
        for (int o = 16; o; o >>= 1) sv += __shfl_xor_sync(0xFFFFFFFFu, sv, o);
        lse[m] = mx + logf(sv);
    }
    __shared__ float sh[8], shm[8];
    if (!lane){
        float lp  = g_sel[t]        - lse[0];
        float rlp = g_sel[NTOK + t] - lse[1];
        float d = rlp - lp;
        float kl = expf(d) - d - 1.f;
        float mk = (float)mask[t];
        sh[wwid]  = (-adv[t >> 10] + 0.1f*kl) * mk;
        shm[wwid] = mk;
    }
    __syncthreads();
    if (!threadIdx.x){
        float s = 0.f, m = 0.f;
        #pragma unroll
        for (int w = 0; w < 8; w++){ s += sh[w]; m += shm[w]; }
        g_bsum[blockIdx.x] = s; g_bmsk[blockIdx.x] = m;
    }
}

__global__ void k_final(float* out){
    float s = 0.f, m = 0.f;
    for (int i = threadIdx.x; i < 512; i += 32){ s += g_bsum[i]; m += g_bmsk[i]; }
    #pragma unroll
    for (int o = 16; o; o >>= 1){
        s += __shfl_xor_sync(0xFFFFFFFFu, s, o);
        m += __shfl_xor_sync(0xFFFFFFFFu, m, o);
    }
    if (!threadIdx.x) out[0] = s / fmaxf(m, 1.f);
}

// ================= launch =====================================================
extern "C" void kernel_launch(void* const* d_in, const int* in_sizes, int n_in,
                              void* d_out, int out_size){
    const float* x   = (const float*)d_in[0];
    const float* w   = (const float*)d_in[1];
    const float* rx  = (const float*)d_in[2];
    const float* rw  = (const float*)d_in[3];
    const float* adv = (const float*)d_in[4];
    const int* ids   = (const int*)d_in[5];
    const int* mask  = (const int*)d_in[6];
    float* out = (float*)d_out;

    cudaFuncSetAttribute(k_gemm, cudaFuncAttributeMaxDynamicSharedMemorySize, DSMEM);

    {   size_t v4 = (size_t)NTOK*HH/4;   // hidden convert
        k_convert<<<(unsigned)((2*v4 + 255)/256), 256>>>(x, rx, g_xb, v4);
    }
    {   size_t v4 = (size_t)VV*HH/4;     // weight convert
        k_convert<<<(unsigned)((2*v4 + 255)/256), 256>>>(w, rw, g_wb, v4);
    }
    k_sel<<<(2*NTOK*32 + 255)/256, 256>>>(x, w, rx, rw, ids);
    k_gemm<<<dim3(VSP, TTL, 2), 256, DSMEM>>>();
    k_reduce<<<512, 256>>>(adv, mask);
    k_final<<<1, 32>>>(out);
}

// round 15
// speedup vs baseline: 1.2783x; 1.2783x over previous
#include <cuda_runtime.h>
#include <cuda_fp8.h>
#include <cuda_fp16.h>
#include <cstdint>

#define NTOK 4096
#define HH   1024
#define VV   32000
#define VSP  125          // 125 * 256 = 32000 vocab splits
#define TTL  32           // 32 * 128 = 4096 token tiles
#define NKC  8            // 8 * 128 = 1024 k-chunks (fp8: 128 elems = 128B)
#define ROWB 128          // 128 fp8 per row, XOR-swizzled
#define ATILE (128*ROWB)  // 16384
#define BTILE (256*ROWB)  // 32768
#define STGB  (ATILE+BTILE) // 49152
#define DSMEM (2*STGB + 128)

// ---------------- device scratch (no allocations allowed) -------------------
__device__ __align__(256) unsigned char g_xb[(size_t)2*NTOK*HH];   // 8.4 MB
__device__ __align__(256) unsigned char g_wb[(size_t)2*VV*HH];     // 65.5 MB
__device__ float g_pm[(size_t)2*NTOK*VSP];
__device__ float g_ps[(size_t)2*NTOK*VSP];
__device__ float g_sel[2*NTOK];
__device__ float g_bsum[512];
__device__ float g_bmsk[512];

__device__ __forceinline__ uint32_t smem_u32(const void* p){
    uint32_t a;
    asm("{ .reg .u64 t; cvta.to.shared.u64 t, %1; cvt.u32.u64 %0, t; }" : "=r"(a) : "l"(p));
    return a;
}

// ================= fp32 -> e4m3 conversion, all four tensors, one launch ====
__global__ void k_convert_all(const float* __restrict__ w,  const float* __restrict__ rw,
                              const float* __restrict__ x,  const float* __restrict__ rx){
    const size_t WV4 = (size_t)VV*256;    // per-model W vec4 count
    const size_t XV4 = (size_t)NTOK*256;  // per-model X vec4 count
    size_t g = (size_t)blockIdx.x*blockDim.x + threadIdx.x;
    if (g >= 2*WV4 + 2*XV4) return;
    const float* src; unsigned char* dst; size_t i;
    if (g < 2*WV4){
        int m = (g >= WV4); i = g - (size_t)m*WV4;
        src = m ? rw : w;  dst = g_wb + (size_t)m*WV4*4;
    } else {
        size_t h = g - 2*WV4;
        int m = (h >= XV4); i = h - (size_t)m*XV4;
        src = m ? rx : x;  dst = g_xb + (size_t)m*XV4*4;
    }
    float4 v = reinterpret_cast<const float4*>(src)[i];
    __nv_fp8x2_storage_t lo = __nv_cvt_float2_to_fp8x2(make_float2(v.x, v.y), __NV_SATFINITE, __NV_E4M3);
    __nv_fp8x2_storage_t hi = __nv_cvt_float2_to_fp8x2(make_float2(v.z, v.w), __NV_SATFINITE, __NV_E4M3);
    reinterpret_cast<uint32_t*>(dst)[i] = (uint32_t)lo | ((uint32_t)hi << 16);
}

// ================= main GEMM (mma e4m3 k32, f16 acc) + fused online-LSE =====
// grid (VSP=125, TTL=32, 2), block 256, CTA tile 128x256, warp tile 64x64.
// R12 pipeline; mma asm NON-volatile so ptxas can software-pipeline across ks.
__global__ void __launch_bounds__(256,2) k_gemm(){
    extern __shared__ __align__(16) unsigned char dsm[];
    const int tid = threadIdx.x, wid = tid>>5, lane = tid&31;
    const int vs = blockIdx.x, tt = blockIdx.y, model = blockIdx.z;
    const int wm = wid>>2, wn = wid&3;
    const uint32_t s0 = (smem_u32(dsm) + 127) & ~127u;
    const unsigned char* asrc0 = g_xb + ((size_t)model*NTOK + (size_t)tt*128)*HH;
    const unsigned char* bsrc0 = g_wb + ((size_t)model*VV   + (size_t)vs*256)*HH;

    const int lq  = tid >> 3;
    const int lg  = tid & 7;
    const uint32_t dA = s0 + lq*ROWB + ((lg ^ (lq & 7)) << 4);
    const uint32_t dB = dA + ATILE;
    const unsigned char* srcA = asrc0 + (size_t)lq*HH + lg*16;
    const unsigned char* srcB = bsrc0 + (size_t)lq*HH + lg*16;

    #define LOADC(kc, so_) do{ \
        const size_t _ko = (size_t)(kc)*128; \
        _Pragma("unroll") \
        for (int it = 0; it < 4; it++) \
            asm volatile("cp.async.cg.shared.global [%0], [%1], 16;" \
                :: "r"(dA + (so_) + it*4096), "l"(srcA + _ko + (size_t)it*32768)); \
        _Pragma("unroll") \
        for (int it = 0; it < 8; it++) \
            asm volatile("cp.async.cg.shared.global [%0], [%1], 16;" \
                :: "r"(dB + (so_) + it*4096), "l"(srcB + _ko + (size_t)it*32768)); \
        asm volatile("cp.async.commit_group;"); \
    }while(0)

    uint32_t KA[4], KB[4];
    {
        const uint32_t half_a = (lane>>4) << 4;
        #pragma unroll
        for (int mt = 0; mt < 4; mt++){
            int row = wm*64 + mt*16 + (lane&15);
            KA[mt] = (s0 + row*ROWB + ((row&7)<<4)) ^ half_a;
        }
        const uint32_t half_b = ((lane>>3)&1) << 4;
        #pragma unroll
        for (int p = 0; p < 4; p++){
            int row = wn*64 + p*16 + (lane&7) + ((lane>>4)<<3);
            KB[p] = (s0 + ATILE + row*ROWB + ((row&7)<<4)) ^ half_b;
        }
    }

    uint32_t acc[4][8][2];
    #pragma unroll
    for (int a=0;a<4;a++)
        #pragma unroll
        for (int b=0;b<8;b++){ acc[a][b][0]=0u; acc[a][b][1]=0u; }

    LOADC(0, 0);
    LOADC(1, STGB);
    uint32_t rso = 0;
    #pragma unroll 1
    for (int kc = 0; kc < NKC; kc++){
        if (kc < NKC-1) asm volatile("cp.async.wait_group 1;");
        else            asm volatile("cp.async.wait_group 0;");
        __syncthreads();
        const uint32_t ar0 = KA[0]+rso, ar1 = KA[1]+rso, ar2 = KA[2]+rso, ar3 = KA[3]+rso;
        const uint32_t br0 = KB[0]+rso, br1 = KB[1]+rso, br2 = KB[2]+rso, br3 = KB[3]+rso;
        #pragma unroll
        for (int ks = 0; ks < 4; ks++){
            const uint32_t xc = ks << 5;
            uint32_t af[4][4], bf[4][4];
            asm volatile("ldmatrix.sync.aligned.m8n8.x4.shared.b16 {%0,%1,%2,%3}, [%4];"
                : "=r"(af[0][0]),"=r"(af[0][1]),"=r"(af[0][2]),"=r"(af[0][3]) : "r"(ar0^xc));
            asm volatile("ldmatrix.sync.aligned.m8n8.x4.shared.b16 {%0,%1,%2,%3}, [%4];"
                : "=r"(af[1][0]),"=r"(af[1][1]),"=r"(af[1][2]),"=r"(af[1][3]) : "r"(ar1^xc));
            asm volatile("ldmatrix.sync.aligned.m8n8.x4.shared.b16 {%0,%1,%2,%3}, [%4];"
                : "=r"(af[2][0]),"=r"(af[2][1]),"=r"(af[2][2]),"=r"(af[2][3]) : "r"(ar2^xc));
            asm volatile("ldmatrix.sync.aligned.m8n8.x4.shared.b16 {%0,%1,%2,%3}, [%4];"
                : "=r"(af[3][0]),"=r"(af[3][1]),"=r"(af[3][2]),"=r"(af[3][3]) : "r"(ar3^xc));
            asm volatile("ldmatrix.sync.aligned.m8n8.x4.shared.b16 {%0,%1,%2,%3}, [%4];"
                : "=r"(bf[0][0]),"=r"(bf[0][1]),"=r"(bf[0][2]),"=r"(bf[0][3]) : "r"(br0^xc));
            asm volatile("ldmatrix.sync.aligned.m8n8.x4.shared.b16 {%0,%1,%2,%3}, [%4];"
                : "=r"(bf[1][0]),"=r"(bf[1][1]),"=r"(bf[1][2]),"=r"(bf[1][3]) : "r"(br1^xc));
            asm volatile("ldmatrix.sync.aligned.m8n8.x4.shared.b16 {%0,%1,%2,%3}, [%4];"
                : "=r"(bf[2][0]),"=r"(bf[2][1]),"=r"(bf[2][2]),"=r"(bf[2][3]) : "r"(br2^xc));
            asm volatile("ldmatrix.sync.aligned.m8n8.x4.shared.b16 {%0,%1,%2,%3}, [%4];"
                : "=r"(bf[3][0]),"=r"(bf[3][1]),"=r"(bf[3][2]),"=r"(bf[3][3]) : "r"(br3^xc));
            #pragma unroll
            for (int mt = 0; mt < 4; mt++)
                #pragma unroll
                for (int nt = 0; nt < 8; nt++){
                    uint32_t c0 = bf[nt>>1][(nt&1)*2], c1 = bf[nt>>1][(nt&1)*2+1];
                    // NON-volatile: ptxas may schedule freely (software pipeline)
                    asm("mma.sync.aligned.m16n8k32.row.col.f16.e4m3.e4m3.f16 "
                        "{%0,%1}, {%2,%3,%4,%5}, {%6,%7}, {%0,%1};"
                        : "+r"(acc[mt][nt][0]),"+r"(acc[mt][nt][1])
                        : "r"(af[mt][0]),"r"(af[mt][1]),"r"(af[mt][2]),"r"(af[mt][3]),
                          "r"(c0),"r"(c1));
                }
        }
        __syncthreads();
        if (kc + 2 < NKC) LOADC(kc+2, rso);
        rso ^= STGB;
    }
    __syncthreads();

    // ---- fused epilogue: per-token-row (max, sumexp) over this 256-col slab -
    float* smM = (float*)dsm;
    float* smS = smM + 8*64;
    int q = lane>>2;
    #pragma unroll
    for (int mt = 0; mt < 4; mt++){
        float m0=-3e38f, m1=-3e38f;
        #pragma unroll
        for (int nt = 0; nt < 8; nt++){
            __half2 h0 = *reinterpret_cast<__half2*>(&acc[mt][nt][0]);
            __half2 h1 = *reinterpret_cast<__half2*>(&acc[mt][nt][1]);
            m0 = fmaxf(m0, fmaxf(__half2float(h0.x), __half2float(h0.y)));
            m1 = fmaxf(m1, fmaxf(__half2float(h1.x), __half2float(h1.y)));
        }
        #pragma unroll
        for (int o = 1; o <= 2; o <<= 1){
            m0 = fmaxf(m0, __shfl_xor_sync(0xFFFFFFFFu, m0, o));
            m1 = fmaxf(m1, __shfl_xor_sync(0xFFFFFFFFu, m1, o));
        }
        float sA = 0.f, sB = 0.f;
        #pragma unroll
        for (int nt = 0; nt < 8; nt++){
            __half2 h0 = *reinterpret_cast<__half2*>(&acc[mt][nt][0]);
            __half2 h1 = *reinterpret_cast<__half2*>(&acc[mt][nt][1]);
            sA += __expf(__half2float(h0.x)-m0) + __expf(__half2float(h0.y)-m0);
            sB += __expf(__half2float(h1.x)-m1) + __expf(__half2float(h1.y)-m1);
        }
        #pragma unroll
        for (int o = 1; o <= 2; o <<= 1){
            sA += __shfl_xor_sync(0xFFFFFFFFu, sA, o);
            sB += __shfl_xor_sync(0xFFFFFFFFu, sB, o);
        }
        if ((lane&3) == 0){
            int r = mt*16 + q;
            smM[wid*64 + r]     = m0;  smS[wid*64 + r]     = sA;
            smM[wid*64 + r + 8] = m1;  smS[wid*64 + r + 8] = sB;
        }
    }
    __syncthreads();
    if (tid < 128){
        int wm2 = tid>>6, r = tid&63;
        float M = -3e38f;
        #pragma unroll
        for (int w = 0; w < 4; w++) M = fmaxf(M, smM[(wm2*4+w)*64 + r]);
        float S = 0.f;
        #pragma unroll
        for (int w = 0; w < 4; w++) S += smS[(wm2*4+w)*64 + r] * __expf(smM[(wm2*4+w)*64 + r] - M);
        int tok = tt*128 + tid;
        size_t o = ((size_t)(model*NTOK + tok))*VSP + vs;
        g_pm[o] = M; g_ps[o] = S;
    }
}

// ================= exact fp32 selected logits ================================
__global__ void k_sel(const float* __restrict__ x, const float* __restrict__ w,
                      const float* __restrict__ rx, const float* __restrict__ rw,
                      const int* __restrict__ ids){
    int gw = (int)((blockIdx.x*blockDim.x + threadIdx.x) >> 5);
    int lane = threadIdx.x & 31;
    if (gw >= 2*NTOK) return;
    int m = gw >> 12, t = gw & (NTOK-1);
    const float* X = m ? rx : x;
    const float* W = m ? rw : w;
    int id = ids[t];
    const float4* xa = (const float4*)(X + (size_t)t*HH);
    const float4* wa = (const float4*)(W + (size_t)id*HH);
    float acc = 0.f;
    #pragma unroll 8
    for (int i = lane; i < 256; i += 32){
        float4 a = xa[i], b = wa[i];
        acc += a.x*b.x + a.y*b.y + a.z*b.z + a.w*b.w;
    }
    #pragma unroll
    for (int o = 16; o; o >>= 1) acc += __shfl_xor_sync(0xFFFFFFFFu, acc, o);
    if (!lane) g_sel[gw] = acc;
}

// ================= warp-per-token loss + deterministic block sums ===========
__global__ void k_reduce(const float* __restrict__ adv, const int* __restrict__ mask){
    const int lane = threadIdx.x & 31, wwid = threadIdx.x >> 5;
    const int t = blockIdx.x*8 + wwid;
    float lse[2];
    #pragma unroll
    for (int m = 0; m < 2; m++){
        const float* pm = g_pm + ((size_t)(m*NTOK + t))*VSP;
        const float* ps = g_ps + ((size_t)(m*NTOK + t))*VSP;
        float mx = -3e38f;
        #pragma unroll
        for (int v = lane; v < VSP; v += 32) mx = fmaxf(mx, pm[v]);
        #pragma unroll
        for (int o = 16; o; o >>= 1) mx = fmaxf(mx, __shfl_xor_sync(0xFFFFFFFFu, mx, o));
        float sv = 0.f;
        #pragma unroll
        for (int v = lane; v < VSP; v += 32) sv += ps[v] * __expf(pm[v] - mx);
        #pragma unroll
        for (int o = 16; o; o >>= 1) sv += __shfl_xor_sync(0xFFFFFFFFu, sv, o);
        lse[m] = mx + logf(sv);
    }
    __shared__ float sh[8], shm[8];
    if (!lane){
        float lp  = g_sel[t]        - lse[0];
        float rlp = g_sel[NTOK + t] - lse[1];
        float d = rlp - lp;
        float kl = expf(d) - d - 1.f;
        float mk = (float)mask[t];
        sh[wwid]  = (-adv[t >> 10] + 0.1f*kl) * mk;
        shm[wwid] = mk;
    }
    __syncthreads();
    if (!threadIdx.x){
        float s = 0.f, m = 0.f;
        #pragma unroll
        for (int w = 0; w < 8; w++){ s += sh[w]; m += shm[w]; }
        g_bsum[blockIdx.x] = s; g_bmsk[blockIdx.x] = m;
    }
}

__global__ void k_final(float* out){
    float s = 0.f, m = 0.f;
    for (int i = threadIdx.x; i < 512; i += 32){ s += g_bsum[i]; m += g_bmsk[i]; }
    #pragma unroll
    for (int o = 16; o; o >>= 1){
        s += __shfl_xor_sync(0xFFFFFFFFu, s, o);
        m += __shfl_xor_sync(0xFFFFFFFFu, m, o);
    }
    if (!threadIdx.x) out[0] = s / fmaxf(m, 1.f);
}

// ================= launch =====================================================
extern "C" void kernel_launch(void* const* d_in, const int* in_sizes, int n_in,
                              void* d_out, int out_size){
    const float* x   = (const float*)d_in[0];
    const float* w   = (const float*)d_in[1];
    const float* rx  = (const float*)d_in[2];
    const float* rw  = (const float*)d_in[3];
    const float* adv = (const float*)d_in[4];
    const int* ids   = (const int*)d_in[5];
    const int* mask  = (const int*)d_in[6];
    float* out = (float*)d_out;

    cudaFuncSetAttribute(k_gemm, cudaFuncAttributeMaxDynamicSharedMemorySize, DSMEM);

    {   size_t tot = (size_t)2*(VV + NTOK)*256;   // all four tensors, one launch
        k_convert_all<<<(unsigned)((tot + 255)/256), 256>>>(w, rw, x, rx);
    }
    k_sel<<<(2*NTOK*32 + 255)/256, 256>>>(x, w, rx, rw, ids);
    k_gemm<<<dim3(VSP, TTL, 2), 256, DSMEM>>>();
    k_reduce<<<512, 256>>>(adv, mask);
    k_final<<<1, 32>>>(out);
}